// round 13
// baseline (speedup 1.0000x reference)
#include <cuda_runtime.h>
#include <cuda_fp16.h>
#include <cstddef>

// SumLayer: out[nids[n], :] = log( sum_e params[pids[n,e]] * exp(element_mars[cids[n,e], :]) )
// N=32768, E=32, B=256, element_mars [65536, 256] fp32.
//
// v9: gather is at the ~15 TB/s LTS cap (measured, done). Remaining harvest
// is the exp pass: it was latency-bound at MLP=2 (DRAM=41%, issue=27%).
// Now each thread issues 4 independent fully-coalesced __ldcs float4 loads
// (CTA tile of 1024 float4s, stride-256) for MLP=4.

constexpr int E    = 32;
constexpr int B    = 256;
constexpr int ROWS = 65536;
constexpr int NPC  = 8;              // nodes per CTA in gather (1 warp/node)

union Vec8h { uint4 u; __half2 h[4]; };
union Vec4h { uint2 u; __half2 h[2]; };

// fp16 scratch: exp(element_mars), ROWS x B halves = 33.5 MB (L2-resident).
__device__ uint4 g_exp[(size_t)ROWS * B / 8];

// ---------------- Pass 1: elementwise exp, fp32 -> fp16, MLP=4 ----------------
// CTA tile = 1024 float4s; thread handles 4 at stride 256 (all coalesced).
__global__ __launch_bounds__(256) void exp_kernel(
    const float4* __restrict__ in, int n4)
{
    const int base = blockIdx.x * 1024 + threadIdx.x;

    // 4 independent streaming loads, front-batched for MLP.
    const float4 v0 = __ldcs(in + base);
    const float4 v1 = __ldcs(in + base + 256);
    const float4 v2 = __ldcs(in + base + 512);
    const float4 v3 = __ldcs(in + base + 768);

    uint2* dst = reinterpret_cast<uint2*>(g_exp);

    Vec4h r0, r1, r2, r3;
    r0.h[0] = __floats2half2_rn(__expf(v0.x), __expf(v0.y));
    r0.h[1] = __floats2half2_rn(__expf(v0.z), __expf(v0.w));
    r1.h[0] = __floats2half2_rn(__expf(v1.x), __expf(v1.y));
    r1.h[1] = __floats2half2_rn(__expf(v1.z), __expf(v1.w));
    r2.h[0] = __floats2half2_rn(__expf(v2.x), __expf(v2.y));
    r2.h[1] = __floats2half2_rn(__expf(v2.z), __expf(v2.w));
    r3.h[0] = __floats2half2_rn(__expf(v3.x), __expf(v3.y));
    r3.h[1] = __floats2half2_rn(__expf(v3.z), __expf(v3.w));

    dst[base]       = r0.u;
    dst[base + 256] = r1.u;
    dst[base + 512] = r2.u;
    dst[base + 768] = r3.u;
}

// ---------------- Pass 2: weighted gather-sum + log (unchanged, at LTS cap) ----------------
__global__ __launch_bounds__(32 * NPC, 8) void gather_kernel(
    const float* __restrict__ params,
    const int*   __restrict__ nids,
    const int*   __restrict__ cids,
    const int*   __restrict__ pids,
    float*       __restrict__ out,
    int          n_nodes)
{
    __shared__ int2 s_cw[NPC][E];        // {cid, weight-bits}

    const int tid  = threadIdx.x;
    const int ln   = tid >> 5;           // warp = node within CTA
    const int lane = tid & 31;
    const int n    = blockIdx.x * NPC + ln;

    if (n < n_nodes) {
        const size_t idx = (size_t)n * E + lane;     // one edge per lane
        s_cw[ln][lane] = make_int2(cids[idx],
                                   __float_as_int(__ldg(params + pids[idx])));
    }
    __syncwarp();                        // staging is warp-private
    if (n >= n_nodes) return;

    // Lane-fixed base: row occupies B/8 = 32 uint4s; lane owns one (16B).
    const uint4* base = g_exp + lane;

    float a0 = 0.f, a1 = 0.f, a2 = 0.f, a3 = 0.f,
          a4 = 0.f, a5 = 0.f, a6 = 0.f, a7 = 0.f;

#pragma unroll
    for (int e = 0; e < E; ++e) {
        const int2  cw = s_cw[ln][e];    // warp-uniform LDS.64 broadcast
        const float w  = __int_as_float(cw.y);
        Vec8h v;
        v.u = base[(size_t)cw.x * (B / 8)];
        const float2 f0 = __half22float2(v.h[0]);
        const float2 f1 = __half22float2(v.h[1]);
        const float2 f2 = __half22float2(v.h[2]);
        const float2 f3 = __half22float2(v.h[3]);
        a0 = fmaf(w, f0.x, a0);  a1 = fmaf(w, f0.y, a1);
        a2 = fmaf(w, f1.x, a2);  a3 = fmaf(w, f1.y, a3);
        a4 = fmaf(w, f2.x, a4);  a5 = fmaf(w, f2.y, a5);
        a6 = fmaf(w, f3.x, a6);  a7 = fmaf(w, f3.y, a7);
    }

    const int nid = nids[n];             // warp-uniform broadcast
    float* orow = out + (size_t)nid * B + lane * 8;
    float4 o0, o1;
    o0.x = __logf(fmaxf(a0, 1e-10f));
    o0.y = __logf(fmaxf(a1, 1e-10f));
    o0.z = __logf(fmaxf(a2, 1e-10f));
    o0.w = __logf(fmaxf(a3, 1e-10f));
    o1.x = __logf(fmaxf(a4, 1e-10f));
    o1.y = __logf(fmaxf(a5, 1e-10f));
    o1.z = __logf(fmaxf(a6, 1e-10f));
    o1.w = __logf(fmaxf(a7, 1e-10f));
    *reinterpret_cast<float4*>(orow)     = o0;
    *reinterpret_cast<float4*>(orow + 4) = o1;
}

extern "C" void kernel_launch(void* const* d_in, const int* in_sizes, int n_in,
                              void* d_out, int out_size)
{
    const float* element_mars = (const float*)d_in[1];
    const float* params       = (const float*)d_in[2];
    const int*   nids         = (const int*)d_in[3];
    const int*   cids         = (const int*)d_in[4];
    const int*   pids         = (const int*)d_in[5];
    float*       out          = (float*)d_out;

    const int N     = in_sizes[3];           // nodes
    const int n_els = in_sizes[1];           // ROWS * B
    const int n4    = n_els / 4;             // float4 count (multiple of 1024)

    exp_kernel<<<n4 / 1024, 256>>>((const float4*)element_mars, n4);

    gather_kernel<<<(N + NPC - 1) / NPC, 32 * NPC>>>(
        params, nids, cids, pids, out, N);
}